// round 4
// baseline (speedup 1.0000x reference)
#include <cuda_runtime.h>
#include <math.h>

#define NNODE 650
#define NPAD  672            // 650 padded to multiple of 32
#define FDIM  512
#define NE    150000
#define ET    150650
#define NJ    16             // FDIM/32 column blocks (partial-logit slices)

// ---------------- device scratch ----------------
__device__ float g_x[NNODE * FDIM];
__device__ float g_h[NNODE * FDIM];
__device__ float g_A[NPAD * NPAD];     // zero-init; rows >= 650 never written, stay 0
__device__ int   g_C[NPAD * NPAD];     // edge count matrix [dst][src]
__device__ float g_alsp[NJ * NPAD];    // partial src logits per column-block
__device__ float g_aldp[NJ * NPAD];    // partial dst logits per column-block
__device__ float g_sum[NNODE];

__device__ __forceinline__ float leaky02(float x) { return fmaxf(x, 0.2f * x); }

__device__ __forceinline__ void fma2(unsigned long long &d,
                                     unsigned long long a,
                                     unsigned long long b) {
    asm("fma.rn.f32x2 %0, %1, %2, %0;" : "+l"(d) : "l"(a), "l"(b));
}
__device__ __forceinline__ float2 upk(unsigned long long v) {
    float2 r; asm("mov.b64 {%0,%1}, %2;" : "=f"(r.x), "=f"(r.y) : "l"(v)); return r;
}

// ---------------- zero count matrix ----------------
__global__ void zeroc_kernel() {
    int i = blockIdx.x * 256 + threadIdx.x;        // NPAD*NPAD/4 = 112896 exactly
    *(int4*)&g_C[i * 4] = make_int4(0, 0, 0, 0);
}

// ---------------- count edges (incl. self loops) ----------------
__global__ void count_kernel(const int* __restrict__ ei) {
    int i = blockIdx.x * 256 + threadIdx.x;
    if (i >= ET) return;
    int s, d;
    if (i < NE) { s = ei[i]; d = ei[NE + i]; }
    else        { s = i - NE; d = s; }
    atomicAdd(&g_C[d * NPAD + s], 1);
}

// ---------------- GEMM: h = X @ W  (+ partial attention logits) --------------
// 32x32 tile, 64 threads, 4x4 microtile via packed f32x2 FMA.
// use_gx==0: X = concat(xs[0:400], xt[0:250]); use_gx==1: X = g_x (device symbol)
__global__ __launch_bounds__(64) void gemm_xw_kernel(const float* __restrict__ xs,
                                                     const float* __restrict__ xt,
                                                     int use_gx,
                                                     const float* __restrict__ W,
                                                     const float* __restrict__ avs,
                                                     const float* __restrict__ avd) {
    __shared__ float As[32][32];   // [k][m]
    __shared__ float Bd[32][64];   // [k][2n] duplicated pairs
    const int tid = threadIdx.x;
    const int bm = blockIdx.y * 32, bn = blockIdx.x * 32;
    const int tr = tid >> 3, tc = tid & 7;
    const int lrow = tid >> 1, half = (tid & 1) * 16;

    const float* abase = nullptr;
    {
        int gr = bm + lrow;
        if (gr < NNODE)
            abase = use_gx ? (g_x + gr * FDIM)
                           : (gr < 400 ? xs + gr * FDIM : xt + (gr - 400) * FDIM);
    }

    unsigned long long acc[2][4] = {{0,0,0,0},{0,0,0,0}};

    for (int k0 = 0; k0 < FDIM; k0 += 32) {
        // A tile -> transposed smem
#pragma unroll
        for (int i = 0; i < 4; i++) {
            float4 v = abase ? *(const float4*)(abase + k0 + half + i * 4)
                             : make_float4(0.f, 0.f, 0.f, 0.f);
            As[half + i*4 + 0][lrow] = v.x;
            As[half + i*4 + 1][lrow] = v.y;
            As[half + i*4 + 2][lrow] = v.z;
            As[half + i*4 + 3][lrow] = v.w;
        }
        // B tile -> duplicated smem
        const float* bp = W + (k0 + lrow) * FDIM + bn + half;
#pragma unroll
        for (int i = 0; i < 4; i++) {
            float4 v = *(const float4*)(bp + i * 4);
            *(float4*)&Bd[lrow][2 * (half + i*4)]     = make_float4(v.x, v.x, v.y, v.y);
            *(float4*)&Bd[lrow][2 * (half + i*4) + 4] = make_float4(v.z, v.z, v.w, v.w);
        }
        __syncthreads();
#pragma unroll
        for (int k = 0; k < 32; k++) {
            ulonglong2 a2  = *(const ulonglong2*)&As[k][tr * 4];
            ulonglong2 b01 = *(const ulonglong2*)&Bd[k][tc * 8];
            ulonglong2 b23 = *(const ulonglong2*)&Bd[k][tc * 8 + 4];
            fma2(acc[0][0], a2.x, b01.x); fma2(acc[1][0], a2.y, b01.x);
            fma2(acc[0][1], a2.x, b01.y); fma2(acc[1][1], a2.y, b01.y);
            fma2(acc[0][2], a2.x, b23.x); fma2(acc[1][2], a2.y, b23.x);
            fma2(acc[0][3], a2.x, b23.y); fma2(acc[1][3], a2.y, b23.y);
        }
        __syncthreads();
    }

    float vals[4][4];
#pragma unroll
    for (int c = 0; c < 4; c++) {
        float2 p0 = upk(acc[0][c]);
        float2 p1 = upk(acc[1][c]);
        vals[0][c] = p0.x; vals[1][c] = p0.y;
        vals[2][c] = p1.x; vals[3][c] = p1.y;
    }
    float4 va = *(const float4*)(avs + bn + tc * 4);
    float4 vd = *(const float4*)(avd + bn + tc * 4);
#pragma unroll
    for (int r = 0; r < 4; r++) {
        int gr = bm + tr * 4 + r;
        if (gr < NNODE)
            *(float4*)&g_h[gr * FDIM + bn + tc * 4] =
                make_float4(vals[r][0], vals[r][1], vals[r][2], vals[r][3]);
        float sa = vals[r][0]*va.x + vals[r][1]*va.y + vals[r][2]*va.z + vals[r][3]*va.w;
        float sd = vals[r][0]*vd.x + vals[r][1]*vd.y + vals[r][2]*vd.z + vals[r][3]*vd.w;
#pragma unroll
        for (int o = 4; o > 0; o >>= 1) {
            sa += __shfl_down_sync(0xffffffffu, sa, o, 8);
            sd += __shfl_down_sync(0xffffffffu, sd, o, 8);
        }
        if (tc == 0 && gr < NNODE) {
            g_alsp[blockIdx.x * NPAD + gr] = sa;
            g_aldp[blockIdx.x * NPAD + gr] = sd;
        }
    }
}

// ---------------- build: finalize logits, global max, A = C*exp(...), row sums
__global__ __launch_bounds__(256) void build_kernel() {
    const int d = blockIdx.x, t = threadIdx.x;
    __shared__ float s_als[NPAD];
    __shared__ float red[256];
    __shared__ float s_ald;

    for (int s = t; s < NPAD; s += 256) {
        float v = 0.f;
        if (s < NNODE) {
#pragma unroll
            for (int j = 0; j < NJ; j++) v += g_alsp[j * NPAD + s];
        }
        s_als[s] = v;
    }
    if (t == 0) {
        float v = 0.f;
#pragma unroll
        for (int j = 0; j < NJ; j++) v += g_aldp[j * NPAD + d];
        s_ald = v;
    }
    __syncthreads();

    // global max over als[0..649] (same value in every block)
    float m = -1e30f;
    for (int s = t; s < NNODE; s += 256) m = fmaxf(m, s_als[s]);
    red[t] = m; __syncthreads();
    for (int o = 128; o > 0; o >>= 1) { if (t < o) red[t] = fmaxf(red[t], red[t + o]); __syncthreads(); }
    const float M = red[0];
    const float ald = s_ald;
    const float mp = leaky02(M + ald);     // valid shift: >= true segment max
    __syncthreads();

    float lsum = 0.f;
    for (int s = t; s < NPAD; s += 256) {
        float p = 0.f;
        if (s < NNODE) {
            int c = g_C[d * NPAD + s];
            if (c) p = (float)c * expf(leaky02(s_als[s] + ald) - mp);
        }
        g_A[d * NPAD + s] = p;
        lsum += p;
    }
    red[t] = lsum; __syncthreads();
    for (int o = 128; o > 0; o >>= 1) { if (t < o) red[t] += red[t + o]; __syncthreads(); }
    if (t == 0) g_sum[d] = red[0];
}

// ---------------- GEMM: out = (A @ h) * inv_sum + b, activation -> g_x -------
__global__ __launch_bounds__(64) void gemm_ah_kernel(const float* __restrict__ bias, int act) {
    __shared__ float As[32][32];
    __shared__ float Bd[32][64];
    const int tid = threadIdx.x;
    const int bm = blockIdx.y * 32, bn = blockIdx.x * 32;
    const int tr = tid >> 3, tc = tid & 7;
    const int lrow = tid >> 1, half = (tid & 1) * 16;

    const float* arow_p = &g_A[(bm + lrow) * NPAD];
    unsigned long long acc[2][4] = {{0,0,0,0},{0,0,0,0}};

    for (int k0 = 0; k0 < NPAD; k0 += 32) {
#pragma unroll
        for (int i = 0; i < 4; i++) {
            float4 v = *(const float4*)(arow_p + k0 + half + i * 4);
            As[half + i*4 + 0][lrow] = v.x;
            As[half + i*4 + 1][lrow] = v.y;
            As[half + i*4 + 2][lrow] = v.z;
            As[half + i*4 + 3][lrow] = v.w;
        }
        int gk = k0 + lrow;
        const float* bp = (gk < NNODE) ? &g_h[gk * FDIM + bn + half] : nullptr;
#pragma unroll
        for (int i = 0; i < 4; i++) {
            float4 v = bp ? *(const float4*)(bp + i * 4) : make_float4(0.f,0.f,0.f,0.f);
            *(float4*)&Bd[lrow][2 * (half + i*4)]     = make_float4(v.x, v.x, v.y, v.y);
            *(float4*)&Bd[lrow][2 * (half + i*4) + 4] = make_float4(v.z, v.z, v.w, v.w);
        }
        __syncthreads();
#pragma unroll
        for (int k = 0; k < 32; k++) {
            ulonglong2 a2  = *(const ulonglong2*)&As[k][tr * 4];
            ulonglong2 b01 = *(const ulonglong2*)&Bd[k][tc * 8];
            ulonglong2 b23 = *(const ulonglong2*)&Bd[k][tc * 8 + 4];
            fma2(acc[0][0], a2.x, b01.x); fma2(acc[1][0], a2.y, b01.x);
            fma2(acc[0][1], a2.x, b01.y); fma2(acc[1][1], a2.y, b01.y);
            fma2(acc[0][2], a2.x, b23.x); fma2(acc[1][2], a2.y, b23.x);
            fma2(acc[0][3], a2.x, b23.y); fma2(acc[1][3], a2.y, b23.y);
        }
        __syncthreads();
    }

    float vals[4][4];
#pragma unroll
    for (int c = 0; c < 4; c++) {
        float2 p0 = upk(acc[0][c]);
        float2 p1 = upk(acc[1][c]);
        vals[0][c] = p0.x; vals[1][c] = p0.y;
        vals[2][c] = p1.x; vals[3][c] = p1.y;
    }
    float4 bv = *(const float4*)(bias + bn + tc * 4);
#pragma unroll
    for (int r = 0; r < 4; r++) {
        int gr = bm + tr * 4 + r;
        if (gr >= NNODE) continue;
        float inv = 1.f / (g_sum[gr] + 1e-16f);
        float v0 = vals[r][0] * inv + bv.x;
        float v1 = vals[r][1] * inv + bv.y;
        float v2 = vals[r][2] * inv + bv.z;
        float v3 = vals[r][3] * inv + bv.w;
        float4 o;
        if (act == 0)
            o = make_float4(fmaxf(v0,0.f), fmaxf(v1,0.f), fmaxf(v2,0.f), fmaxf(v3,0.f));
        else
            o = make_float4(v0>0.f?v0:0.01f*v0, v1>0.f?v1:0.01f*v1,
                            v2>0.f?v2:0.01f*v2, v3>0.f?v3:0.01f*v3);
        *(float4*)&g_x[gr * FDIM + bn + tc * 4] = o;
    }
}

// ---------------- fc + sigmoid ----------------
__global__ __launch_bounds__(256) void fc_kernel(const float* __restrict__ fcw,
                                                 const float* __restrict__ fcb,
                                                 float* __restrict__ out) {
    int j = blockIdx.x;
    int t = threadIdx.x;
    float acc = 0.f;
    const float* y = &g_x[j * NNODE];     // flat .view: [512][650]
    for (int k = t; k < NNODE; k += 256) acc += y[k] * fcw[k];
    __shared__ float r[256];
    r[t] = acc; __syncthreads();
    for (int s = 128; s > 0; s >>= 1) { if (t < s) r[t] += r[t + s]; __syncthreads(); }
    if (t == 0) out[j] = 1.f / (1.f + expf(-(r[0] + fcb[0])));
}

// ---------------- launch ----------------
extern "C" void kernel_launch(void* const* d_in, const int* in_sizes, int n_in,
                              void* d_out, int out_size) {
    const float* x_s = (const float*)d_in[0];
    const float* x_t = (const float*)d_in[1];
    const int*   ei  = (const int*)  d_in[2];
    const float* W1  = (const float*)d_in[5];
    const float* as1 = (const float*)d_in[6];
    const float* ad1 = (const float*)d_in[7];
    const float* b1  = (const float*)d_in[8];
    const float* W4  = (const float*)d_in[9];
    const float* as4 = (const float*)d_in[10];
    const float* ad4 = (const float*)d_in[11];
    const float* b4  = (const float*)d_in[12];
    const float* fcw = (const float*)d_in[13];
    const float* fcb = (const float*)d_in[14];
    float* out = (float*)d_out;

    dim3 ggrid(FDIM / 32, NPAD / 32);              // 16 x 21 = 336 blocks

    zeroc_kernel<<<NPAD * NPAD / 4 / 256, 256>>>();        // 441 blocks, exact
    count_kernel<<<(ET + 255) / 256, 256>>>(ei);

    // layer 1
    gemm_xw_kernel<<<ggrid, 64>>>(x_s, x_t, 0, W1, as1, ad1);
    build_kernel<<<NNODE, 256>>>();
    gemm_ah_kernel<<<ggrid, 64>>>(b1, 0);          // relu

    // layer 2
    gemm_xw_kernel<<<ggrid, 64>>>(x_s, x_t, 1, W4, as4, ad4);
    build_kernel<<<NNODE, 256>>>();
    gemm_ah_kernel<<<ggrid, 64>>>(b4, 1);          // leaky 0.01

    fc_kernel<<<FDIM, 256>>>(fcw, fcb, out);
}

// round 7
// speedup vs baseline: 2.0281x; 2.0281x over previous
#include <cuda_runtime.h>
#include <math.h>

#define NNODE 650
#define NPAD  672            // 650 padded to multiple of 32
#define FDIM  512
#define NE    150000
#define ET    150650
#define NJ    8              // FDIM/64 column blocks (partial-logit slices)

// ---------------- device scratch ----------------
__device__ float g_x[NNODE * FDIM];
__device__ float g_h[NNODE * FDIM];
__device__ float g_A[NPAD * NPAD];     // rows >= 650 never written -> stay zero
__device__ int   g_C[NPAD * NPAD];     // edge count matrix [dst][src]
__device__ float g_alsp[NJ * NPAD];    // partial src logits per column-block
__device__ float g_aldp[NJ * NPAD];    // partial dst logits per column-block
__device__ float g_sum[NNODE];

__device__ __forceinline__ float leaky02(float x) { return fmaxf(x, 0.2f * x); }

// ---------------- zero count matrix ----------------
__global__ void zeroc_kernel() {
    int i = blockIdx.x * 256 + threadIdx.x;      // NPAD*NPAD/4 = 112896 exactly
    *(int4*)&g_C[i * 4] = make_int4(0, 0, 0, 0);
}

// ---------------- count edges (incl. self loops) ----------------
__global__ void count_kernel(const int* __restrict__ ei) {
    int i = blockIdx.x * 256 + threadIdx.x;
    if (i >= ET) return;
    int s, d;
    if (i < NE) { s = ei[i]; d = ei[NE + i]; }
    else        { s = i - NE; d = s; }
    atomicAdd(&g_C[d * NPAD + s], 1);
}

// ---------------- GEMM: h = X @ W (+ partial attention logits) ---------------
// BM=32 BN=64 BK=32, 128 threads, 4x4 microtile
__global__ __launch_bounds__(128) void gemm_xw_kernel(const float* __restrict__ xs,
                                                      const float* __restrict__ xt,
                                                      int use_gx,
                                                      const float* __restrict__ W,
                                                      const float* __restrict__ avs,
                                                      const float* __restrict__ avd) {
    __shared__ float As[32][36];   // [k][m], 16B-aligned rows
    __shared__ float Bs[32][68];   // [k][n]
    const int tid = threadIdx.x;
    const int bm = blockIdx.y * 32, bn = blockIdx.x * 64;
    const int tr = tid >> 4, tc = tid & 15;          // 8 x 16 thread grid
    const int arow = tid >> 2, acol = (tid & 3) * 8; // A tile load mapping
    const int brow = tid >> 4, bcol = (tid & 15) * 4;

    const float* abase = nullptr;
    {
        int gr = bm + arow;
        if (gr < NNODE)
            abase = use_gx ? (g_x + gr * FDIM)
                           : (gr < 400 ? xs + gr * FDIM : xt + (gr - 400) * FDIM);
    }

    float acc[4][4] = {{0,0,0,0},{0,0,0,0},{0,0,0,0},{0,0,0,0}};

    for (int k0 = 0; k0 < FDIM; k0 += 32) {
        float4 a0 = make_float4(0.f,0.f,0.f,0.f), a1 = a0;
        if (abase) {
            a0 = *(const float4*)(abase + k0 + acol);
            a1 = *(const float4*)(abase + k0 + acol + 4);
        }
        As[acol+0][arow]=a0.x; As[acol+1][arow]=a0.y;
        As[acol+2][arow]=a0.z; As[acol+3][arow]=a0.w;
        As[acol+4][arow]=a1.x; As[acol+5][arow]=a1.y;
        As[acol+6][arow]=a1.z; As[acol+7][arow]=a1.w;
#pragma unroll
        for (int j = 0; j < 4; j++) {
            int kr = brow + j * 8;
            *(float4*)&Bs[kr][bcol] = *(const float4*)(W + (k0 + kr) * FDIM + bn + bcol);
        }
        __syncthreads();
#pragma unroll
        for (int k = 0; k < 32; k++) {
            float4 a = *(const float4*)&As[k][tr * 4];
            float4 b = *(const float4*)&Bs[k][tc * 4];
            acc[0][0]+=a.x*b.x; acc[0][1]+=a.x*b.y; acc[0][2]+=a.x*b.z; acc[0][3]+=a.x*b.w;
            acc[1][0]+=a.y*b.x; acc[1][1]+=a.y*b.y; acc[1][2]+=a.y*b.z; acc[1][3]+=a.y*b.w;
            acc[2][0]+=a.z*b.x; acc[2][1]+=a.z*b.y; acc[2][2]+=a.z*b.z; acc[2][3]+=a.z*b.w;
            acc[3][0]+=a.w*b.x; acc[3][1]+=a.w*b.y; acc[3][2]+=a.w*b.z; acc[3][3]+=a.w*b.w;
        }
        __syncthreads();
    }

    float4 va = *(const float4*)(avs + bn + tc * 4);
    float4 vd = *(const float4*)(avd + bn + tc * 4);
#pragma unroll
    for (int r = 0; r < 4; r++) {
        int gr = bm + tr * 4 + r;
        if (gr < NNODE)
            *(float4*)&g_h[gr * FDIM + bn + tc * 4] =
                make_float4(acc[r][0], acc[r][1], acc[r][2], acc[r][3]);
        float sa = acc[r][0]*va.x + acc[r][1]*va.y + acc[r][2]*va.z + acc[r][3]*va.w;
        float sd = acc[r][0]*vd.x + acc[r][1]*vd.y + acc[r][2]*vd.z + acc[r][3]*vd.w;
#pragma unroll
        for (int o = 8; o > 0; o >>= 1) {
            sa += __shfl_down_sync(0xffffffffu, sa, o, 16);
            sd += __shfl_down_sync(0xffffffffu, sd, o, 16);
        }
        if (tc == 0 && gr < NNODE) {
            g_alsp[blockIdx.x * NPAD + gr] = sa;
            g_aldp[blockIdx.x * NPAD + gr] = sd;
        }
    }
}

// ---------------- build: finalize logits, global max, A = C*exp(...), row sums
__global__ __launch_bounds__(256) void build_kernel() {
    const int d = blockIdx.x, t = threadIdx.x;
    __shared__ float s_als[NPAD];
    __shared__ float red[256];
    __shared__ float s_ald;

    for (int s = t; s < NPAD; s += 256) {
        float v = 0.f;
        if (s < NNODE) {
#pragma unroll
            for (int j = 0; j < NJ; j++) v += g_alsp[j * NPAD + s];
        }
        s_als[s] = v;
    }
    if (t == 0) {
        float v = 0.f;
#pragma unroll
        for (int j = 0; j < NJ; j++) v += g_aldp[j * NPAD + d];
        s_ald = v;
    }
    __syncthreads();

    float m = -1e30f;
    for (int s = t; s < NNODE; s += 256) m = fmaxf(m, s_als[s]);
    red[t] = m; __syncthreads();
    for (int o = 128; o > 0; o >>= 1) { if (t < o) red[t] = fmaxf(red[t], red[t + o]); __syncthreads(); }
    const float M = red[0];
    const float ald = s_ald;
    const float mp = leaky02(M + ald);     // valid shift: >= true segment max
    __syncthreads();

    float lsum = 0.f;
    for (int s = t; s < NPAD; s += 256) {
        float p = 0.f;
        if (s < NNODE) {
            int c = g_C[d * NPAD + s];
            if (c) p = (float)c * expf(leaky02(s_als[s] + ald) - mp);
        }
        g_A[d * NPAD + s] = p;
        lsum += p;
    }
    red[t] = lsum; __syncthreads();
    for (int o = 128; o > 0; o >>= 1) { if (t < o) red[t] += red[t + o]; __syncthreads(); }
    if (t == 0) g_sum[d] = red[0];
}

// ---------------- GEMM: out = (A @ h) * inv_sum + b, activation -> g_x -------
__global__ __launch_bounds__(128) void gemm_ah_kernel(const float* __restrict__ bias, int act) {
    __shared__ float As[32][36];
    __shared__ float Bs[32][68];
    const int tid = threadIdx.x;
    const int bm = blockIdx.y * 32, bn = blockIdx.x * 64;
    const int tr = tid >> 4, tc = tid & 15;
    const int arow = tid >> 2, acol = (tid & 3) * 8;
    const int brow = tid >> 4, bcol = (tid & 15) * 4;

    const float* arow_p = &g_A[(bm + arow) * NPAD];   // rows < 672 always valid
    float acc[4][4] = {{0,0,0,0},{0,0,0,0},{0,0,0,0},{0,0,0,0}};

    for (int k0 = 0; k0 < NPAD; k0 += 32) {
        float4 a0 = *(const float4*)(arow_p + k0 + acol);
        float4 a1 = *(const float4*)(arow_p + k0 + acol + 4);
        As[acol+0][arow]=a0.x; As[acol+1][arow]=a0.y;
        As[acol+2][arow]=a0.z; As[acol+3][arow]=a0.w;
        As[acol+4][arow]=a1.x; As[acol+5][arow]=a1.y;
        As[acol+6][arow]=a1.z; As[acol+7][arow]=a1.w;
#pragma unroll
        for (int j = 0; j < 4; j++) {
            int kr = k0 + brow + j * 8;
            float4 v = (kr < NNODE) ? *(const float4*)(&g_h[kr * FDIM + bn + bcol])
                                    : make_float4(0.f,0.f,0.f,0.f);
            *(float4*)&Bs[brow + j * 8][bcol] = v;
        }
        __syncthreads();
#pragma unroll
        for (int k = 0; k < 32; k++) {
            float4 a = *(const float4*)&As[k][tr * 4];
            float4 b = *(const float4*)&Bs[k][tc * 4];
            acc[0][0]+=a.x*b.x; acc[0][1]+=a.x*b.y; acc[0][2]+=a.x*b.z; acc[0][3]+=a.x*b.w;
            acc[1][0]+=a.y*b.x; acc[1][1]+=a.y*b.y; acc[1][2]+=a.y*b.z; acc[1][3]+=a.y*b.w;
            acc[2][0]+=a.z*b.x; acc[2][1]+=a.z*b.y; acc[2][2]+=a.z*b.z; acc[2][3]+=a.z*b.w;
            acc[3][0]+=a.w*b.x; acc[3][1]+=a.w*b.y; acc[3][2]+=a.w*b.z; acc[3][3]+=a.w*b.w;
        }
        __syncthreads();
    }

    float4 bv = *(const float4*)(bias + bn + tc * 4);
#pragma unroll
    for (int r = 0; r < 4; r++) {
        int gr = bm + tr * 4 + r;
        if (gr >= NNODE) continue;
        float inv = 1.f / (g_sum[gr] + 1e-16f);
        float v0 = acc[r][0] * inv + bv.x;
        float v1 = acc[r][1] * inv + bv.y;
        float v2 = acc[r][2] * inv + bv.z;
        float v3 = acc[r][3] * inv + bv.w;
        float4 o;
        if (act == 0)
            o = make_float4(fmaxf(v0,0.f), fmaxf(v1,0.f), fmaxf(v2,0.f), fmaxf(v3,0.f));
        else
            o = make_float4(v0>0.f?v0:0.01f*v0, v1>0.f?v1:0.01f*v1,
                            v2>0.f?v2:0.01f*v2, v3>0.f?v3:0.01f*v3);
        *(float4*)&g_x[gr * FDIM + bn + tc * 4] = o;
    }
}

// ---------------- fc + sigmoid ----------------
__global__ __launch_bounds__(256) void fc_kernel(const float* __restrict__ fcw,
                                                 const float* __restrict__ fcb,
                                                 float* __restrict__ out) {
    int j = blockIdx.x;
    int t = threadIdx.x;
    float acc = 0.f;
    const float* y = &g_x[j * NNODE];     // flat .view: [512][650]
    for (int k = t; k < NNODE; k += 256) acc += y[k] * fcw[k];
    __shared__ float r[256];
    r[t] = acc; __syncthreads();
    for (int s = 128; s > 0; s >>= 1) { if (t < s) r[t] += r[t + s]; __syncthreads(); }
    if (t == 0) out[j] = 1.f / (1.f + expf(-(r[0] + fcb[0])));
}

// ---------------- launch ----------------
extern "C" void kernel_launch(void* const* d_in, const int* in_sizes, int n_in,
                              void* d_out, int out_size) {
    const float* x_s = (const float*)d_in[0];
    const float* x_t = (const float*)d_in[1];
    const int*   ei  = (const int*)  d_in[2];
    const float* W1  = (const float*)d_in[5];
    const float* as1 = (const float*)d_in[6];
    const float* ad1 = (const float*)d_in[7];
    const float* b1  = (const float*)d_in[8];
    const float* W4  = (const float*)d_in[9];
    const float* as4 = (const float*)d_in[10];
    const float* ad4 = (const float*)d_in[11];
    const float* b4  = (const float*)d_in[12];
    const float* fcw = (const float*)d_in[13];
    const float* fcb = (const float*)d_in[14];
    float* out = (float*)d_out;

    dim3 ggrid(FDIM / 64, NPAD / 32);              // 8 x 21 = 168 blocks

    zeroc_kernel<<<NPAD * NPAD / 4 / 256, 256>>>();
    count_kernel<<<(ET + 255) / 256, 256>>>(ei);

    // layer 1
    gemm_xw_kernel<<<ggrid, 128>>>(x_s, x_t, 0, W1, as1, ad1);
    build_kernel<<<NNODE, 256>>>();
    gemm_ah_kernel<<<ggrid, 128>>>(b1, 0);         // relu

    // layer 2
    gemm_xw_kernel<<<ggrid, 128>>>(x_s, x_t, 1, W4, as4, ad4);
    build_kernel<<<NNODE, 256>>>();
    gemm_ah_kernel<<<ggrid, 128>>>(b4, 1);         // leaky 0.01

    fc_kernel<<<FDIM, 256>>>(fcw, fcb, out);
}